// round 5
// baseline (speedup 1.0000x reference)
#include <cuda_runtime.h>
#include <cuda_bf16.h>
#include <cstdint>

#define TT 512
#define BB 64
#define II 256
#define HH 1024
#define OO 128
#define NCTA 128   // scan grid: 16 nt-groups x 8 k-splits

// ---------------- scratch (device globals; no allocation allowed) ----------------
static __device__ __nv_bfloat16 g_x0[TT * BB * II];   // x [T,B,I], bf16 hi
static __device__ __nv_bfloat16 g_x1[TT * BB * II];   // bf16 lo
static __device__ __nv_bfloat16 g_wih0[HH * II];
static __device__ __nv_bfloat16 g_wih1[HH * II];
static __device__ __nv_bfloat16 g_whh0[HH * HH];
static __device__ __nv_bfloat16 g_whh1[HH * HH];
static __device__ float         g_xp[(size_t)TT * BB * HH];  // [t][j][b]; scan red.adds into it
static __device__ __nv_bfloat16 g_h0[3 * BB * HH];           // h hi, [buf][j][b]
static __device__ __nv_bfloat16 g_h1[3 * BB * HH];           // h lo
static __device__ float         g_hT[BB * HH];               // h_512, [b][j] for final linear
static __device__ unsigned      g_flag[16 * 8];              // h-ready epoch per group (32B pad)
static __device__ unsigned      g_cnt[16 * 8];               // arrival counter per group

// ---------------- helpers ----------------
__device__ __forceinline__ unsigned ld_acq(const unsigned* p) {
    unsigned v;
    asm volatile("ld.acquire.gpu.u32 %0, [%1];" : "=r"(v) : "l"(p) : "memory");
    return v;
}
__device__ __forceinline__ void st_rel(unsigned* p, unsigned v) {
    asm volatile("st.release.gpu.u32 [%0], %1;" ::"l"(p), "r"(v) : "memory");
}
__device__ __forceinline__ void red_f32(float* p, float v) {
    asm volatile("red.relaxed.gpu.global.add.f32 [%0], %1;" ::"l"(p), "f"(v) : "memory");
}
__device__ __forceinline__ unsigned atom_arrive(unsigned* p) {
    unsigned v;
    asm volatile("atom.acq_rel.gpu.global.add.u32 %0, [%1], 1;" : "=r"(v) : "l"(p) : "memory");
    return v;
}

__device__ __forceinline__ uint32_t smem_u32(const void* p) {
    uint32_t a;
    asm("{ .reg .u64 t; cvta.to.shared.u64 t, %1; cvt.u32.u64 %0, t; }" : "=r"(a) : "l"(p));
    return a;
}

__device__ __forceinline__ float ftanh(float x) {
    float xx = fminf(fmaxf(x, -15.0f), 15.0f);
    float e = __expf(2.0f * xx);
    return __fdividef(e - 1.0f, e + 1.0f);
}

__device__ __forceinline__ void mma16816(float& d0, float& d1, float& d2, float& d3,
                                         unsigned a0, unsigned a1, unsigned a2, unsigned a3,
                                         unsigned b0, unsigned b1) {
    asm volatile(
        "mma.sync.aligned.m16n8k16.row.col.f32.bf16.bf16.f32 "
        "{%0,%1,%2,%3},{%4,%5,%6,%7},{%8,%9},{%0,%1,%2,%3};\n"
        : "+f"(d0), "+f"(d1), "+f"(d2), "+f"(d3)
        : "r"(a0), "r"(a1), "r"(a2), "r"(a3), "r"(b0), "r"(b1));
}

__device__ __forceinline__ void ldsm_x4(unsigned& r0, unsigned& r1, unsigned& r2, unsigned& r3,
                                        uint32_t addr) {
    asm volatile("ldmatrix.sync.aligned.m8n8.x4.shared.b16 {%0,%1,%2,%3}, [%4];"
                 : "=r"(r0), "=r"(r1), "=r"(r2), "=r"(r3) : "r"(addr));
}
__device__ __forceinline__ void ldsm_x4t(unsigned& r0, unsigned& r1, unsigned& r2, unsigned& r3,
                                         uint32_t addr) {
    asm volatile("ldmatrix.sync.aligned.m8n8.x4.trans.shared.b16 {%0,%1,%2,%3}, [%4];"
                 : "=r"(r0), "=r"(r1), "=r"(r2), "=r"(r3) : "r"(addr));
}

__device__ __forceinline__ void cp16(uint32_t dst, const void* src) {
    asm volatile("cp.async.cg.shared.global [%0], [%1], 16;" ::"r"(dst), "l"(src) : "memory");
}

template <int COLS, int PAD>
__device__ __forceinline__ void copy_tile(__nv_bfloat16* dst, const __nv_bfloat16* src,
                                          int src_stride) {
    constexpr int U4R = COLS / 8;
    constexpr int TOT = 64 * U4R;
#pragma unroll 4
    for (int it = threadIdx.x; it < TOT; it += 256) {
        int r = it / U4R;
        int c = (it % U4R) * 8;
        *reinterpret_cast<uint4*>(dst + r * PAD + c) =
            *reinterpret_cast<const uint4*>(src + r * src_stride + c);
    }
}

// ---------------- split / init kernels ----------------
__global__ void split_x_kernel(const float* __restrict__ x) {
    int i = blockIdx.x * 256 + threadIdx.x;
    int ii = i & (II - 1);
    int tb = i >> 8;
    int b = tb & (BB - 1);
    int t = tb >> 6;
    float v = x[((size_t)(b * TT + t) << 8) + ii];
    __nv_bfloat16 h = __float2bfloat16(v);
    g_x0[i] = h;
    g_x1[i] = __float2bfloat16(v - __bfloat162float(h));
}

__global__ void split_wih_kernel(const float* __restrict__ w) {
    int i = blockIdx.x * 256 + threadIdx.x;
    float v = w[i];
    __nv_bfloat16 h = __float2bfloat16(v);
    g_wih0[i] = h;
    g_wih1[i] = __float2bfloat16(v - __bfloat162float(h));
}

__global__ void split_whh_kernel(const float* __restrict__ w) {
    int i = blockIdx.x * 256 + threadIdx.x;
    float v = w[i];
    __nv_bfloat16 h = __float2bfloat16(v);
    g_whh0[i] = h;
    g_whh1[i] = __float2bfloat16(v - __bfloat162float(h));
}

__global__ void init_kernel() {
    int i = blockIdx.x * 256 + threadIdx.x;   // 65536 threads
    __nv_bfloat16 z = __float2bfloat16(0.0f);
    g_h0[i] = z;        // buffer 0 (= h_0 state)
    g_h1[i] = z;
    if (i < 16 * 8) {
        g_flag[i] = 0u;
        g_cnt[i] = 0u;
    }
}

// ---------------- phase 1: xp[t][j][b] = (x @ W_ih^T + b_ih + b_hh)^T ----------------
__global__ void __launch_bounds__(256, 1)
xp_gemm_kernel(const float* __restrict__ b_ih, const float* __restrict__ b_hh) {
    extern __shared__ __align__(16) unsigned char smem_raw[];
    __nv_bfloat16* sx0 = reinterpret_cast<__nv_bfloat16*>(smem_raw);
    __nv_bfloat16* sx1 = sx0 + 64 * 264;
    __nv_bfloat16* sw0 = sx1 + 64 * 264;
    __nv_bfloat16* sw1 = sw0 + 64 * 264;

    const int mt = blockIdx.x;   // = t (64 batch rows)
    const int nt = blockIdx.y;   // hidden tile

    copy_tile<256, 264>(sx0, g_x0 + (size_t)(mt * 64) * II, II);
    copy_tile<256, 264>(sx1, g_x1 + (size_t)(mt * 64) * II, II);
    copy_tile<256, 264>(sw0, g_wih0 + (size_t)(nt * 64) * II, II);
    copy_tile<256, 264>(sw1, g_wih1 + (size_t)(nt * 64) * II, II);
    __syncthreads();

    const int warp = threadIdx.x >> 5, lane = threadIdx.x & 31;
    const int m0 = (warp >> 1) << 4;
    const int n0 = (warp & 1) << 5;
    const int gr = lane >> 2;
    const int qc = (lane & 3) << 1;

    float d[4][4] = {};
#pragma unroll
    for (int seg = 0; seg < 3; ++seg) {
        const __nv_bfloat16* A = (seg < 2) ? sx0 : sx1;
        const __nv_bfloat16* Bm = (seg == 1) ? sw1 : sw0;
        const __nv_bfloat16* ar = A + (m0 + gr) * 264 + qc;
#pragma unroll 4
        for (int kk = 0; kk < 256; kk += 16) {
            unsigned a0 = *reinterpret_cast<const unsigned*>(ar + kk);
            unsigned a1 = *reinterpret_cast<const unsigned*>(ar + kk + 8 * 264);
            unsigned a2 = *reinterpret_cast<const unsigned*>(ar + kk + 8);
            unsigned a3 = *reinterpret_cast<const unsigned*>(ar + kk + 8 * 264 + 8);
#pragma unroll
            for (int nj = 0; nj < 4; ++nj) {
                const __nv_bfloat16* bp = Bm + (n0 + nj * 8 + gr) * 264 + kk + qc;
                unsigned b0 = *reinterpret_cast<const unsigned*>(bp);
                unsigned b1 = *reinterpret_cast<const unsigned*>(bp + 8);
                mma16816(d[nj][0], d[nj][1], d[nj][2], d[nj][3], a0, a1, a2, a3, b0, b1);
            }
        }
    }

    // transposed store: xp[t=mt][j][b]
    const int bb = m0 + gr;
    const int colg = nt * 64 + n0 + qc;
    float* outb = g_xp + (size_t)mt * (BB * HH);
#pragma unroll
    for (int nj = 0; nj < 4; ++nj) {
        int j = colg + nj * 8;
        float bsA = b_ih[j] + b_hh[j];
        float bsB = b_ih[j + 1] + b_hh[j + 1];
        outb[(size_t)j * 64 + bb] = d[nj][0] + bsA;
        outb[(size_t)(j + 1) * 64 + bb] = d[nj][1] + bsB;
        outb[(size_t)j * 64 + bb + 8] = d[nj][2] + bsA;
        outb[(size_t)(j + 1) * 64 + bb + 8] = d[nj][3] + bsB;
    }
}

// ---------------- phase 2: persistent scan, 1-hop atomic reduction ----------------
// CTA bid: nt = bid>>3 (j-rows nt*64..+64), ks = bid&7 (k-window ks*128..+128).
// Per step: poll h flags -> cp.async h -> MMA -> red.add partial into g_xp[t]
//           -> arrive on cnt[nt]; 8th arriver loads reduced slice, tanh, stores h, flag.
__global__ void __launch_bounds__(256, 1) rnn_scan_kernel() {
    extern __shared__ __align__(16) unsigned char smem_raw[];
    __nv_bfloat16* sw0 = reinterpret_cast<__nv_bfloat16*>(smem_raw);   // W0: 64j x 128k (pad 136)
    __nv_bfloat16* sw1 = sw0 + 64 * 136;
    __nv_bfloat16* sh0 = sw1 + 64 * 136;   // h0: 128k x 64b (pad 72)
    __nv_bfloat16* sh1 = sh0 + 128 * 72;
    __shared__ int s_writer;

    const int tid = threadIdx.x;
    const int bid = blockIdx.x;
    const int nt = bid >> 3;
    const int ks = bid & 7;

    copy_tile<128, 136>(sw0, g_whh0 + (size_t)(nt * 64) * HH + ks * 128, HH);
    copy_tile<128, 136>(sw1, g_whh1 + (size_t)(nt * 64) * HH + ks * 128, HH);
    __syncthreads();

    const int warp = tid >> 5, lane = tid & 31;
    const int m0 = (warp >> 1) << 4;   // j sub-tile
    const int n0 = (warp & 1) << 5;    // b half
    const int gr = lane >> 2;
    const int qc = (lane & 3) << 1;

    // hoist W fragments into registers for all 512 steps
    const uint32_t uW0 = smem_u32(sw0), uW1 = smem_u32(sw1);
    const uint32_t a_off = (uint32_t)((m0 + (lane & 15)) * 272 + (lane >> 4) * 16);
    unsigned W0f[8][4], W1f[8][4];
#pragma unroll
    for (int kk = 0; kk < 8; ++kk) {
        ldsm_x4(W0f[kk][0], W0f[kk][1], W0f[kk][2], W0f[kk][3], uW0 + a_off + kk * 32);
        ldsm_x4(W1f[kk][0], W1f[kk][1], W1f[kk][2], W1f[kk][3], uW1 + a_off + kk * 32);
    }

    const uint32_t uH0 = smem_u32(sh0), uH1 = smem_u32(sh1);
    const uint32_t hb_off = (uint32_t)((lane & 15) * 144 + ((lane >> 4) * 8 + n0) * 2);

    const unsigned* const f_poll = g_flag + (2 * ks + (tid & 1)) * 8;   // threads 0,1
    unsigned* const cnt_my = g_cnt + nt * 8;
    unsigned* const flag_my = g_flag + nt * 8;

    for (int t = 0; t < TT; ++t) {
        // ---- wait h_t ready (2 producer-group flags; trivially true at t=0) ----
        if (tid < 2) {
            while ((int)ld_acq(f_poll) < t) {}
        }
        __syncthreads();

        // ---- async-load h tiles from buffer t%3, rows k = ks*128..+128 ----
        const __nv_bfloat16* hb0 = g_h0 + (t % 3) * (BB * HH) + ks * 128 * 64;
        const __nv_bfloat16* hb1 = g_h1 + (t % 3) * (BB * HH) + ks * 128 * 64;
#pragma unroll
        for (int i = 0; i < 4; ++i) {
            int it = tid + i * 256;
            int r = it >> 3, c = it & 7;
            cp16(uH0 + r * 144 + c * 16, hb0 + r * 64 + c * 8);
            cp16(uH1 + r * 144 + c * 16, hb1 + r * 64 + c * 8);
        }
        asm volatile("cp.async.commit_group;" ::: "memory");
        asm volatile("cp.async.wait_group 0;" ::: "memory");
        __syncthreads();

        // ---- MMA: D[j16 x b32] += W0*h0 + W1*h0 + W0*h1 ----
        float d[4][4] = {};
#pragma unroll
        for (int kk = 0; kk < 8; ++kk) {
            unsigned r0, r1, r2, r3, s0, s1, s2, s3;
            ldsm_x4t(r0, r1, r2, r3, uH0 + hb_off + kk * 2304);
            ldsm_x4t(s0, s1, s2, s3, uH0 + hb_off + kk * 2304 + 32);
            mma16816(d[0][0], d[0][1], d[0][2], d[0][3],
                     W0f[kk][0], W0f[kk][1], W0f[kk][2], W0f[kk][3], r0, r1);
            mma16816(d[1][0], d[1][1], d[1][2], d[1][3],
                     W0f[kk][0], W0f[kk][1], W0f[kk][2], W0f[kk][3], r2, r3);
            mma16816(d[2][0], d[2][1], d[2][2], d[2][3],
                     W0f[kk][0], W0f[kk][1], W0f[kk][2], W0f[kk][3], s0, s1);
            mma16816(d[3][0], d[3][1], d[3][2], d[3][3],
                     W0f[kk][0], W0f[kk][1], W0f[kk][2], W0f[kk][3], s2, s3);
            mma16816(d[0][0], d[0][1], d[0][2], d[0][3],
                     W1f[kk][0], W1f[kk][1], W1f[kk][2], W1f[kk][3], r0, r1);
            mma16816(d[1][0], d[1][1], d[1][2], d[1][3],
                     W1f[kk][0], W1f[kk][1], W1f[kk][2], W1f[kk][3], r2, r3);
            mma16816(d[2][0], d[2][1], d[2][2], d[2][3],
                     W1f[kk][0], W1f[kk][1], W1f[kk][2], W1f[kk][3], s0, s1);
            mma16816(d[3][0], d[3][1], d[3][2], d[3][3],
                     W1f[kk][0], W1f[kk][1], W1f[kk][2], W1f[kk][3], s2, s3);
        }
#pragma unroll
        for (int kk = 0; kk < 8; ++kk) {
            unsigned r0, r1, r2, r3, s0, s1, s2, s3;
            ldsm_x4t(r0, r1, r2, r3, uH1 + hb_off + kk * 2304);
            ldsm_x4t(s0, s1, s2, s3, uH1 + hb_off + kk * 2304 + 32);
            mma16816(d[0][0], d[0][1], d[0][2], d[0][3],
                     W0f[kk][0], W0f[kk][1], W0f[kk][2], W0f[kk][3], r0, r1);
            mma16816(d[1][0], d[1][1], d[1][2], d[1][3],
                     W0f[kk][0], W0f[kk][1], W0f[kk][2], W0f[kk][3], r2, r3);
            mma16816(d[2][0], d[2][1], d[2][2], d[2][3],
                     W0f[kk][0], W0f[kk][1], W0f[kk][2], W0f[kk][3], s0, s1);
            mma16816(d[3][0], d[3][1], d[3][2], d[3][3],
                     W0f[kk][0], W0f[kk][1], W0f[kk][2], W0f[kk][3], s2, s3);
        }

        // ---- reduce partial into g_xp[t] via L2 atomics (no return) ----
        float* Pp = g_xp + (size_t)t * (BB * HH) +
                    (size_t)(nt * 64 + m0 + gr) * 64 + n0 + qc;
#pragma unroll
        for (int nj = 0; nj < 4; ++nj) {
            red_f32(Pp + nj * 8, d[nj][0]);
            red_f32(Pp + nj * 8 + 1, d[nj][1]);
            red_f32(Pp + nj * 8 + 8 * 64, d[nj][2]);
            red_f32(Pp + nj * 8 + 8 * 64 + 1, d[nj][3]);
        }
        __syncthreads();
        if (tid == 0) {
            unsigned prev = atom_arrive(cnt_my);
            s_writer = (prev == (unsigned)(t * 8 + 7)) ? 1 : 0;
        }
        __syncthreads();

        // ---- 8th arriver: load reduced slice, tanh, split, publish h_{t+1} ----
        if (s_writer) {
            const float* src = g_xp + (size_t)t * (BB * HH) + nt * 4096 + tid * 16;
            float4 a0 = __ldcg(reinterpret_cast<const float4*>(src));
            float4 a1 = __ldcg(reinterpret_cast<const float4*>(src + 4));
            float4 a2 = __ldcg(reinterpret_cast<const float4*>(src + 8));
            float4 a3 = __ldcg(reinterpret_cast<const float4*>(src + 12));
            float v[16] = {a0.x, a0.y, a0.z, a0.w, a1.x, a1.y, a1.z, a1.w,
                           a2.x, a2.y, a2.z, a2.w, a3.x, a3.y, a3.z, a3.w};
#pragma unroll
            for (int i = 0; i < 16; ++i) v[i] = ftanh(v[i]);

            const int ob = ((t + 1) % 3) * (BB * HH) + nt * 4096 + tid * 16;
#pragma unroll
            for (int pq = 0; pq < 8; ++pq) {
                __nv_bfloat162 hiv;
                hiv.x = __float2bfloat16(v[2 * pq]);
                hiv.y = __float2bfloat16(v[2 * pq + 1]);
                *reinterpret_cast<__nv_bfloat162*>(g_h0 + ob + 2 * pq) = hiv;
                __nv_bfloat162 lov;
                lov.x = __float2bfloat16(v[2 * pq] - __bfloat162float(hiv.x));
                lov.y = __float2bfloat16(v[2 * pq + 1] - __bfloat162float(hiv.y));
                *reinterpret_cast<__nv_bfloat162*>(g_h1 + ob + 2 * pq) = lov;
            }
            if (t == TT - 1) {   // h_512 transposed [b][j] in f32 for final linear
                const int jg = nt * 64 + (tid >> 2);
                const int b0 = (tid & 3) * 16;
#pragma unroll
                for (int i = 0; i < 16; ++i) g_hT[(size_t)(b0 + i) * HH + jg] = v[i];
            }
            __syncthreads();
            if (tid == 0) st_rel(flag_my, (unsigned)(t + 1));
        }
    }
}

// ---------------- phase 3: out = h_last @ W_lin^T + b_lin ----------------
__global__ void final_linear_kernel(const float* __restrict__ wlin,
                                    const float* __restrict__ blin,
                                    float* __restrict__ out) {
    int gw = (blockIdx.x * 256 + threadIdx.x) >> 5;
    int lane = threadIdx.x & 31;
    int b = gw >> 7;
    int o = gw & (OO - 1);
    const float* wr = wlin + (size_t)o * HH;
    const float* hr = g_hT + (size_t)b * HH;
    float sum = 0.0f;
#pragma unroll 8
    for (int k = lane; k < HH; k += 32) sum += hr[k] * wr[k];
#pragma unroll
    for (int off = 16; off > 0; off >>= 1) sum += __shfl_down_sync(0xffffffffu, sum, off);
    if (lane == 0) out[b * OO + o] = sum + blin[o];
}

// ---------------- launch ----------------
extern "C" void kernel_launch(void* const* d_in, const int* in_sizes, int n_in,
                              void* d_out, int out_size) {
    (void)in_sizes; (void)n_in; (void)out_size;
    const float* x     = (const float*)d_in[0];
    const float* W_ih  = (const float*)d_in[1];
    const float* W_hh  = (const float*)d_in[2];
    const float* b_ih  = (const float*)d_in[3];
    const float* b_hh  = (const float*)d_in[4];
    const float* W_lin = (const float*)d_in[5];
    const float* b_lin = (const float*)d_in[6];
    float* out = (float*)d_out;

    const int scan_smem = (2 * 64 * 136 + 2 * 128 * 72) * 2;   // 71680 bytes
    cudaFuncSetAttribute(xp_gemm_kernel, cudaFuncAttributeMaxDynamicSharedMemorySize,
                         4 * 64 * 264 * 2);
    cudaFuncSetAttribute(rnn_scan_kernel, cudaFuncAttributeMaxDynamicSharedMemorySize,
                         scan_smem);

    split_x_kernel<<<(TT * BB * II) / 256, 256>>>(x);
    split_wih_kernel<<<(HH * II) / 256, 256>>>(W_ih);
    split_whh_kernel<<<(HH * HH) / 256, 256>>>(W_hh);
    init_kernel<<<(BB * HH) / 256, 256>>>();

    xp_gemm_kernel<<<dim3(512, 16), 256, 4 * 64 * 264 * 2>>>(b_ih, b_hh);
    rnn_scan_kernel<<<NCTA, 256, scan_smem>>>();
    final_linear_kernel<<<(BB * OO * 32) / 256, 256>>>(W_lin, b_lin, out);
}

// round 6
// speedup vs baseline: 1.3856x; 1.3856x over previous
#include <cuda_runtime.h>
#include <cuda_bf16.h>
#include <cstdint>

#define TT 512
#define BB 64
#define II 256
#define HH 1024
#define OO 128
#define NCTA 128   // scan grid: 16 nt-groups x 8 k-splits

// ---------------- scratch (device globals; no allocation allowed) ----------------
static __device__ __nv_bfloat16 g_x0[TT * BB * II];   // x [T,B,I], bf16 hi
static __device__ __nv_bfloat16 g_x1[TT * BB * II];   // bf16 lo
static __device__ __nv_bfloat16 g_wih0[HH * II];
static __device__ __nv_bfloat16 g_wih1[HH * II];
static __device__ __nv_bfloat16 g_whh0[HH * HH];
static __device__ __nv_bfloat16 g_whh1[HH * HH];
static __device__ float         g_xp[(size_t)TT * BB * HH];  // [t][j][b]  (transposed)
static __device__ float         g_part[2 * 8 * BB * HH];     // [parity][ks][j][b]
static __device__ __nv_bfloat16 g_h0[3 * BB * HH];           // h hi, [buf][j][b]
static __device__ __nv_bfloat16 g_h1[3 * BB * HH];           // h lo
static __device__ float         g_hT[BB * HH];               // h_512, [b][j] for final linear
static __device__ unsigned      g_flagA[NCTA * 8];           // partials-ready (32B padded)
static __device__ unsigned      g_flagB[NCTA * 8];           // h-ready

// ---------------- helpers ----------------
__device__ __forceinline__ unsigned ld_acq(const unsigned* p) {
    unsigned v;
    asm volatile("ld.acquire.gpu.u32 %0, [%1];" : "=r"(v) : "l"(p) : "memory");
    return v;
}
__device__ __forceinline__ void st_rel(unsigned* p, unsigned v) {
    asm volatile("st.release.gpu.u32 [%0], %1;" ::"l"(p), "r"(v) : "memory");
}

__device__ __forceinline__ uint32_t smem_u32(const void* p) {
    uint32_t a;
    asm("{ .reg .u64 t; cvta.to.shared.u64 t, %1; cvt.u32.u64 %0, t; }" : "=r"(a) : "l"(p));
    return a;
}

__device__ __forceinline__ void mma16816(float& d0, float& d1, float& d2, float& d3,
                                         unsigned a0, unsigned a1, unsigned a2, unsigned a3,
                                         unsigned b0, unsigned b1) {
    asm volatile(
        "mma.sync.aligned.m16n8k16.row.col.f32.bf16.bf16.f32 "
        "{%0,%1,%2,%3},{%4,%5,%6,%7},{%8,%9},{%0,%1,%2,%3};\n"
        : "+f"(d0), "+f"(d1), "+f"(d2), "+f"(d3)
        : "r"(a0), "r"(a1), "r"(a2), "r"(a3), "r"(b0), "r"(b1));
}

__device__ __forceinline__ void ldsm_x4(unsigned& r0, unsigned& r1, unsigned& r2, unsigned& r3,
                                        uint32_t addr) {
    asm volatile("ldmatrix.sync.aligned.m8n8.x4.shared.b16 {%0,%1,%2,%3}, [%4];"
                 : "=r"(r0), "=r"(r1), "=r"(r2), "=r"(r3) : "r"(addr));
}
__device__ __forceinline__ void ldsm_x4t(unsigned& r0, unsigned& r1, unsigned& r2, unsigned& r3,
                                         uint32_t addr) {
    asm volatile("ldmatrix.sync.aligned.m8n8.x4.trans.shared.b16 {%0,%1,%2,%3}, [%4];"
                 : "=r"(r0), "=r"(r1), "=r"(r2), "=r"(r3) : "r"(addr));
}

__device__ __forceinline__ void cp16(uint32_t dst, const void* src) {
    asm volatile("cp.async.ca.shared.global [%0], [%1], 16;" ::"r"(dst), "l"(src) : "memory");
}

template <int COLS, int PAD>
__device__ __forceinline__ void copy_tile(__nv_bfloat16* dst, const __nv_bfloat16* src,
                                          int src_stride) {
    constexpr int U4R = COLS / 8;
    constexpr int TOT = 64 * U4R;
#pragma unroll 4
    for (int it = threadIdx.x; it < TOT; it += 256) {
        int r = it / U4R;
        int c = (it % U4R) * 8;
        *reinterpret_cast<uint4*>(dst + r * PAD + c) =
            *reinterpret_cast<const uint4*>(src + r * src_stride + c);
    }
}

// ---------------- fused prep: splits + h init + flags (one launch) ----------------
// grid layout: [0, 32768)   -> x split (8.4M elems)
//              [32768, 36864) -> whh split (1M)
//              [36864, 37888) -> wih split (256K)
//              [37888, 38144) -> h/flag init (64K)
__global__ void fused_prep_kernel(const float* __restrict__ x,
                                  const float* __restrict__ W_ih,
                                  const float* __restrict__ W_hh) {
    int blk = blockIdx.x;
    if (blk < 32768) {
        int i = blk * 256 + threadIdx.x;
        int ii = i & (II - 1);
        int tb = i >> 8;
        int b = tb & (BB - 1);
        int t = tb >> 6;
        float v = x[((size_t)(b * TT + t) << 8) + ii];
        __nv_bfloat16 h = __float2bfloat16(v);
        g_x0[i] = h;
        g_x1[i] = __float2bfloat16(v - __bfloat162float(h));
    } else if (blk < 36864) {
        int i = (blk - 32768) * 256 + threadIdx.x;
        float v = W_hh[i];
        __nv_bfloat16 h = __float2bfloat16(v);
        g_whh0[i] = h;
        g_whh1[i] = __float2bfloat16(v - __bfloat162float(h));
    } else if (blk < 37888) {
        int i = (blk - 36864) * 256 + threadIdx.x;
        float v = W_ih[i];
        __nv_bfloat16 h = __float2bfloat16(v);
        g_wih0[i] = h;
        g_wih1[i] = __float2bfloat16(v - __bfloat162float(h));
    } else {
        int i = (blk - 37888) * 256 + threadIdx.x;
        __nv_bfloat16 z = __float2bfloat16(0.0f);
        g_h0[i] = z;   // buffer 0 = h_0
        g_h1[i] = z;
        if (i < NCTA * 8) {
            g_flagA[i] = 0u;
            g_flagB[i] = 0u;
        }
    }
}

// no-op spacer so rnn_scan is the 4th launch (ncu captures launch #4)
__global__ void spacer_kernel() {}

// ---------------- phase 1: xp[t][j][b] = (x @ W_ih^T + b_ih + b_hh)^T ----------------
__global__ void __launch_bounds__(256, 1)
xp_gemm_kernel(const float* __restrict__ b_ih, const float* __restrict__ b_hh) {
    extern __shared__ __align__(16) unsigned char smem_raw[];
    __nv_bfloat16* sx0 = reinterpret_cast<__nv_bfloat16*>(smem_raw);
    __nv_bfloat16* sx1 = sx0 + 64 * 264;
    __nv_bfloat16* sw0 = sx1 + 64 * 264;
    __nv_bfloat16* sw1 = sw0 + 64 * 264;

    const int mt = blockIdx.x;   // = t (64 batch rows)
    const int nt = blockIdx.y;   // hidden tile

    copy_tile<256, 264>(sx0, g_x0 + (size_t)(mt * 64) * II, II);
    copy_tile<256, 264>(sx1, g_x1 + (size_t)(mt * 64) * II, II);
    copy_tile<256, 264>(sw0, g_wih0 + (size_t)(nt * 64) * II, II);
    copy_tile<256, 264>(sw1, g_wih1 + (size_t)(nt * 64) * II, II);
    __syncthreads();

    const int warp = threadIdx.x >> 5, lane = threadIdx.x & 31;
    const int m0 = (warp >> 1) << 4;
    const int n0 = (warp & 1) << 5;
    const int gr = lane >> 2;
    const int qc = (lane & 3) << 1;

    float d[4][4] = {};
#pragma unroll
    for (int seg = 0; seg < 3; ++seg) {
        const __nv_bfloat16* A = (seg < 2) ? sx0 : sx1;
        const __nv_bfloat16* Bm = (seg == 1) ? sw1 : sw0;
        const __nv_bfloat16* ar = A + (m0 + gr) * 264 + qc;
#pragma unroll 4
        for (int kk = 0; kk < 256; kk += 16) {
            unsigned a0 = *reinterpret_cast<const unsigned*>(ar + kk);
            unsigned a1 = *reinterpret_cast<const unsigned*>(ar + kk + 8 * 264);
            unsigned a2 = *reinterpret_cast<const unsigned*>(ar + kk + 8);
            unsigned a3 = *reinterpret_cast<const unsigned*>(ar + kk + 8 * 264 + 8);
#pragma unroll
            for (int nj = 0; nj < 4; ++nj) {
                const __nv_bfloat16* bp = Bm + (n0 + nj * 8 + gr) * 264 + kk + qc;
                unsigned b0 = *reinterpret_cast<const unsigned*>(bp);
                unsigned b1 = *reinterpret_cast<const unsigned*>(bp + 8);
                mma16816(d[nj][0], d[nj][1], d[nj][2], d[nj][3], a0, a1, a2, a3, b0, b1);
            }
        }
    }

    // transposed store: xp[t=mt][j][b]
    const int bb = m0 + gr;
    const int colg = nt * 64 + n0 + qc;
    float* outb = g_xp + (size_t)mt * (BB * HH);
#pragma unroll
    for (int nj = 0; nj < 4; ++nj) {
        int j = colg + nj * 8;
        float bsA = b_ih[j] + b_hh[j];
        float bsB = b_ih[j + 1] + b_hh[j + 1];
        outb[(size_t)j * 64 + bb] = d[nj][0] + bsA;
        outb[(size_t)(j + 1) * 64 + bb] = d[nj][1] + bsB;
        outb[(size_t)j * 64 + bb + 8] = d[nj][2] + bsA;
        outb[(size_t)(j + 1) * 64 + bb + 8] = d[nj][3] + bsB;
    }
}

// ---------------- phase 2: persistent scan, point-to-point flag sync (R4 structure) ----------------
__global__ void __launch_bounds__(256, 1) rnn_scan_kernel() {
    extern __shared__ __align__(16) unsigned char smem_raw[];
    __nv_bfloat16* sw0 = reinterpret_cast<__nv_bfloat16*>(smem_raw);       // W0: 64j x 128k (pad 136)
    __nv_bfloat16* sw1 = sw0 + 64 * 136;
    __nv_bfloat16* sh0 = sw1 + 64 * 136;   // h0: 128k x 64b (pad 72)
    __nv_bfloat16* sh1 = sh0 + 128 * 72;

    const int tid = threadIdx.x;
    const int bid = blockIdx.x;
    const int nt = bid >> 3;
    const int ks = bid & 7;

    copy_tile<128, 136>(sw0, g_whh0 + (size_t)(nt * 64) * HH + ks * 128, HH);
    copy_tile<128, 136>(sw1, g_whh1 + (size_t)(nt * 64) * HH + ks * 128, HH);
    __syncthreads();

    const int warp = tid >> 5, lane = tid & 31;
    const int m0 = (warp >> 1) << 4;   // j sub-tile
    const int n0 = (warp & 1) << 5;    // b half
    const int gr = lane >> 2;
    const int qc = (lane & 3) << 1;

    // hoist W fragments into registers for all 512 steps
    const uint32_t uW0 = smem_u32(sw0), uW1 = smem_u32(sw1);
    const uint32_t a_off = (uint32_t)((m0 + (lane & 15)) * 272 + (lane >> 4) * 16);
    unsigned W0f[8][4], W1f[8][4];
#pragma unroll
    for (int kk = 0; kk < 8; ++kk) {
        ldsm_x4(W0f[kk][0], W0f[kk][1], W0f[kk][2], W0f[kk][3], uW0 + a_off + kk * 32);
        ldsm_x4(W1f[kk][0], W1f[kk][1], W1f[kk][2], W1f[kk][3], uW1 + a_off + kk * 32);
    }

    const uint32_t uH0 = smem_u32(sh0), uH1 = smem_u32(sh1);
    const uint32_t hb_off = (uint32_t)((lane & 15) * 144 + ((lane >> 4) * 8 + n0) * 2);

    unsigned* const fA_my = g_flagA + bid * 8;
    unsigned* const fB_my = g_flagB + bid * 8;
    const unsigned* const fB_poll = g_flagB + (ks * 16 + (tid & 15)) * 8;
    const unsigned* const fA_poll = g_flagA + (nt * 8 + (tid & 7)) * 8;
    const int slice = bid * 512 + tid * 2;

    for (int t = 0; t < TT; ++t) {
        const unsigned p = (unsigned)(t & 1);

        // ---- wait h_t (16 producer flags; trivially satisfied at t=0) ----
        if (tid < 16) {
            while (ld_acq(fB_poll) != p) {}
        }
        __syncthreads();

        // ---- async-load h tiles from buffer t%3, rows k = ks*128..+128 ----
        const __nv_bfloat16* hb0 = g_h0 + (t % 3) * (BB * HH) + ks * 128 * 64;
        const __nv_bfloat16* hb1 = g_h1 + (t % 3) * (BB * HH) + ks * 128 * 64;
#pragma unroll
        for (int i = 0; i < 4; ++i) {
            int it = tid + i * 256;
            int r = it >> 3, c = it & 7;
            cp16(uH0 + r * 144 + c * 16, hb0 + r * 64 + c * 8);
            cp16(uH1 + r * 144 + c * 16, hb1 + r * 64 + c * 8);
        }
        asm volatile("cp.async.commit_group;" ::: "memory");
        // prefetch xp[t] slice for reduce stage
        float2 acc = *reinterpret_cast<const float2*>(g_xp + (size_t)t * (BB * HH) + slice);
        asm volatile("cp.async.wait_group 0;" ::: "memory");
        __syncthreads();

        // ---- MMA: D[j16 x b32] += W0*h0 + W1*h0 + W0*h1 ----
        float d[4][4] = {};
#pragma unroll
        for (int kk = 0; kk < 8; ++kk) {
            unsigned r0, r1, r2, r3, s0, s1, s2, s3;
            ldsm_x4t(r0, r1, r2, r3, uH0 + hb_off + kk * 2304);
            ldsm_x4t(s0, s1, s2, s3, uH0 + hb_off + kk * 2304 + 32);
            mma16816(d[0][0], d[0][1], d[0][2], d[0][3],
                     W0f[kk][0], W0f[kk][1], W0f[kk][2], W0f[kk][3], r0, r1);
            mma16816(d[1][0], d[1][1], d[1][2], d[1][3],
                     W0f[kk][0], W0f[kk][1], W0f[kk][2], W0f[kk][3], r2, r3);
            mma16816(d[2][0], d[2][1], d[2][2], d[2][3],
                     W0f[kk][0], W0f[kk][1], W0f[kk][2], W0f[kk][3], s0, s1);
            mma16816(d[3][0], d[3][1], d[3][2], d[3][3],
                     W0f[kk][0], W0f[kk][1], W0f[kk][2], W0f[kk][3], s2, s3);
            mma16816(d[0][0], d[0][1], d[0][2], d[0][3],
                     W1f[kk][0], W1f[kk][1], W1f[kk][2], W1f[kk][3], r0, r1);
            mma16816(d[1][0], d[1][1], d[1][2], d[1][3],
                     W1f[kk][0], W1f[kk][1], W1f[kk][2], W1f[kk][3], r2, r3);
            mma16816(d[2][0], d[2][1], d[2][2], d[2][3],
                     W1f[kk][0], W1f[kk][1], W1f[kk][2], W1f[kk][3], s0, s1);
            mma16816(d[3][0], d[3][1], d[3][2], d[3][3],
                     W1f[kk][0], W1f[kk][1], W1f[kk][2], W1f[kk][3], s2, s3);
        }
#pragma unroll
        for (int kk = 0; kk < 8; ++kk) {
            unsigned r0, r1, r2, r3, s0, s1, s2, s3;
            ldsm_x4t(r0, r1, r2, r3, uH1 + hb_off + kk * 2304);
            ldsm_x4t(s0, s1, s2, s3, uH1 + hb_off + kk * 2304 + 32);
            mma16816(d[0][0], d[0][1], d[0][2], d[0][3],
                     W0f[kk][0], W0f[kk][1], W0f[kk][2], W0f[kk][3], r0, r1);
            mma16816(d[1][0], d[1][1], d[1][2], d[1][3],
                     W0f[kk][0], W0f[kk][1], W0f[kk][2], W0f[kk][3], r2, r3);
            mma16816(d[2][0], d[2][1], d[2][2], d[2][3],
                     W0f[kk][0], W0f[kk][1], W0f[kk][2], W0f[kk][3], s0, s1);
            mma16816(d[3][0], d[3][1], d[3][2], d[3][3],
                     W0f[kk][0], W0f[kk][1], W0f[kk][2], W0f[kk][3], s2, s3);
        }

        // ---- store partials [parity][ks][j][b] ----
        float* Pp = g_part + ((size_t)p * 8 + ks) * (BB * HH) +
                    (size_t)(nt * 64 + m0 + gr) * 64 + n0 + qc;
#pragma unroll
        for (int nj = 0; nj < 4; ++nj) {
            *reinterpret_cast<float2*>(Pp + nj * 8) = make_float2(d[nj][0], d[nj][1]);
            *reinterpret_cast<float2*>(Pp + nj * 8 + 8 * 64) = make_float2(d[nj][2], d[nj][3]);
        }
        __syncthreads();
        if (tid == 0) st_rel(fA_my, p ^ 1u);

        // ---- wait partials of my nt-group (8 flags, includes own) ----
        if (tid < 8) {
            while (ld_acq(fA_poll) != (p ^ 1u)) {}
        }
        __syncthreads();

        // ---- reduce + tanh + split; write h_{t+1} into buffer (t+1)%3 ----
        {
            float sx = acc.x, sy = acc.y;
#pragma unroll
            for (int s = 0; s < 8; ++s) {
                float2 q = *reinterpret_cast<const float2*>(
                    g_part + ((size_t)p * 8 + s) * (BB * HH) + slice);
                sx += q.x;
                sy += q.y;
            }
            float hx = tanhf(sx), hy = tanhf(sy);
            int ob = ((t + 1) % 3) * (BB * HH) + slice;
            __nv_bfloat162 v0;
            v0.x = __float2bfloat16(hx);
            v0.y = __float2bfloat16(hy);
            *reinterpret_cast<__nv_bfloat162*>(g_h0 + ob) = v0;
            __nv_bfloat162 v1;
            v1.x = __float2bfloat16(hx - __bfloat162float(v0.x));
            v1.y = __float2bfloat16(hy - __bfloat162float(v0.y));
            *reinterpret_cast<__nv_bfloat162*>(g_h1 + ob) = v1;
            if (t == TT - 1) {   // h_512 transposed [b][j] in f32
                int j = slice >> 6, b = slice & 63;
                g_hT[(size_t)b * HH + j] = hx;
                g_hT[(size_t)(b + 1) * HH + j] = hy;
            }
        }
        __syncthreads();
        if (tid == 0) st_rel(fB_my, p ^ 1u);
    }
}

// ---------------- phase 3: out = h_last @ W_lin^T + b_lin ----------------
__global__ void final_linear_kernel(const float* __restrict__ wlin,
                                    const float* __restrict__ blin,
                                    float* __restrict__ out) {
    int gw = (blockIdx.x * 256 + threadIdx.x) >> 5;
    int lane = threadIdx.x & 31;
    int b = gw >> 7;
    int o = gw & (OO - 1);
    const float* wr = wlin + (size_t)o * HH;
    const float* hr = g_hT + (size_t)b * HH;
    float sum = 0.0f;
#pragma unroll 8
    for (int k = lane; k < HH; k += 32) sum += hr[k] * wr[k];
#pragma unroll
    for (int off = 16; off > 0; off >>= 1) sum += __shfl_down_sync(0xffffffffu, sum, off);
    if (lane == 0) out[b * OO + o] = sum + blin[o];
}

// ---------------- launch ----------------
extern "C" void kernel_launch(void* const* d_in, const int* in_sizes, int n_in,
                              void* d_out, int out_size) {
    (void)in_sizes; (void)n_in; (void)out_size;
    const float* x     = (const float*)d_in[0];
    const float* W_ih  = (const float*)d_in[1];
    const float* W_hh  = (const float*)d_in[2];
    const float* b_ih  = (const float*)d_in[3];
    const float* b_hh  = (const float*)d_in[4];
    const float* W_lin = (const float*)d_in[5];
    const float* b_lin = (const float*)d_in[6];
    float* out = (float*)d_out;

    const int scan_smem = (2 * 64 * 136 + 2 * 128 * 72) * 2;   // 71680 bytes
    cudaFuncSetAttribute(xp_gemm_kernel, cudaFuncAttributeMaxDynamicSharedMemorySize,
                         4 * 64 * 264 * 2);
    cudaFuncSetAttribute(rnn_scan_kernel, cudaFuncAttributeMaxDynamicSharedMemorySize,
                         scan_smem);

    fused_prep_kernel<<<38144, 256>>>(x, W_ih, W_hh);                     // launch 1
    xp_gemm_kernel<<<dim3(512, 16), 256, 4 * 64 * 264 * 2>>>(b_ih, b_hh); // launch 2
    spacer_kernel<<<1, 32>>>();                                           // launch 3
    rnn_scan_kernel<<<NCTA, 256, scan_smem>>>();                          // launch 4 (ncu target)
    final_linear_kernel<<<(BB * OO * 32) / 256, 256>>>(W_lin, b_lin, out);
}

// round 8
// speedup vs baseline: 1.3944x; 1.0064x over previous
#include <cuda_runtime.h>
#include <cuda_bf16.h>
#include <cstdint>

#define TT 512
#define BB 64
#define II 256
#define HH 1024
#define OO 128
#define NCTA 128   // scan grid: 16 nt-groups x 8 k-splits

// ---------------- scratch (device globals; no allocation allowed) ----------------
static __device__ __nv_bfloat16 g_x0[TT * BB * II];   // x [T,B,I], bf16 hi
static __device__ __nv_bfloat16 g_x1[TT * BB * II];   // bf16 lo
static __device__ __nv_bfloat16 g_wih0[HH * II];
static __device__ __nv_bfloat16 g_wih1[HH * II];
static __device__ __nv_bfloat16 g_whh0[HH * HH];
static __device__ __nv_bfloat16 g_whh1[HH * HH];
static __device__ float         g_xp[(size_t)TT * BB * HH];  // [t][j][b]  (transposed)
static __device__ float         g_part[2 * 8 * BB * HH];     // [parity][ks][j][b]
// h buffers: [buf][k-window(8)][SW128-swizzled 16KB block]; 128KB per buf per split
static __device__ __nv_bfloat16 g_h0[3 * BB * HH];
static __device__ __nv_bfloat16 g_h1[3 * BB * HH];
static __device__ float         g_hT[BB * HH];               // h_512, [b][j] for final linear
static __device__ unsigned      g_flagA[NCTA * 8];           // partials-ready (32B padded)
static __device__ unsigned      g_flagB[NCTA * 8];           // h-slice-ready

// ---------------- helpers ----------------
__device__ __forceinline__ unsigned ld_acq(const unsigned* p) {
    unsigned v;
    asm volatile("ld.acquire.gpu.u32 %0, [%1];" : "=r"(v) : "l"(p) : "memory");
    return v;
}
__device__ __forceinline__ void st_rel(unsigned* p, unsigned v) {
    asm volatile("st.release.gpu.u32 [%0], %1;" ::"l"(p), "r"(v) : "memory");
}

__device__ __forceinline__ uint32_t smem_u32(const void* p) {
    uint32_t a;
    asm("{ .reg .u64 t; cvta.to.shared.u64 t, %1; cvt.u32.u64 %0, t; }" : "=r"(a) : "l"(p));
    return a;
}

__device__ __forceinline__ void mma16816(float& d0, float& d1, float& d2, float& d3,
                                         unsigned a0, unsigned a1, unsigned a2, unsigned a3,
                                         unsigned b0, unsigned b1) {
    asm volatile(
        "mma.sync.aligned.m16n8k16.row.col.f32.bf16.bf16.f32 "
        "{%0,%1,%2,%3},{%4,%5,%6,%7},{%8,%9},{%0,%1,%2,%3};\n"
        : "+f"(d0), "+f"(d1), "+f"(d2), "+f"(d3)
        : "r"(a0), "r"(a1), "r"(a2), "r"(a3), "r"(b0), "r"(b1));
}

__device__ __forceinline__ void ldsm_x4(unsigned& r0, unsigned& r1, unsigned& r2, unsigned& r3,
                                        uint32_t addr) {
    asm volatile("ldmatrix.sync.aligned.m8n8.x4.shared.b16 {%0,%1,%2,%3}, [%4];"
                 : "=r"(r0), "=r"(r1), "=r"(r2), "=r"(r3) : "r"(addr));
}
__device__ __forceinline__ void ldsm_x4t(unsigned& r0, unsigned& r1, unsigned& r2, unsigned& r3,
                                         uint32_t addr) {
    asm volatile("ldmatrix.sync.aligned.m8n8.x4.trans.shared.b16 {%0,%1,%2,%3}, [%4];"
                 : "=r"(r0), "=r"(r1), "=r"(r2), "=r"(r3) : "r"(addr));
}

template <int COLS, int PAD>
__device__ __forceinline__ void copy_tile(__nv_bfloat16* dst, const __nv_bfloat16* src,
                                          int src_stride) {
    constexpr int U4R = COLS / 8;
    constexpr int TOT = 64 * U4R;
#pragma unroll 4
    for (int it = threadIdx.x; it < TOT; it += 256) {
        int r = it / U4R;
        int c = (it % U4R) * 8;
        *reinterpret_cast<uint4*>(dst + r * PAD + c) =
            *reinterpret_cast<const uint4*>(src + r * src_stride + c);
    }
}

// ---------------- fused prep: splits + h init + flags (one launch) ----------------
__global__ void fused_prep_kernel(const float* __restrict__ x,
                                  const float* __restrict__ W_ih,
                                  const float* __restrict__ W_hh) {
    int blk = blockIdx.x;
    if (blk < 32768) {
        int i = blk * 256 + threadIdx.x;
        int ii = i & (II - 1);
        int tb = i >> 8;
        int b = tb & (BB - 1);
        int t = tb >> 6;
        float v = x[((size_t)(b * TT + t) << 8) + ii];
        __nv_bfloat16 h = __float2bfloat16(v);
        g_x0[i] = h;
        g_x1[i] = __float2bfloat16(v - __bfloat162float(h));
    } else if (blk < 36864) {
        int i = (blk - 32768) * 256 + threadIdx.x;
        float v = W_hh[i];
        __nv_bfloat16 h = __float2bfloat16(v);
        g_whh0[i] = h;
        g_whh1[i] = __float2bfloat16(v - __bfloat162float(h));
    } else if (blk < 37888) {
        int i = (blk - 36864) * 256 + threadIdx.x;
        float v = W_ih[i];
        __nv_bfloat16 h = __float2bfloat16(v);
        g_wih0[i] = h;
        g_wih1[i] = __float2bfloat16(v - __bfloat162float(h));
    } else {
        int i = (blk - 37888) * 256 + threadIdx.x;
        __nv_bfloat16 z = __float2bfloat16(0.0f);
        g_h0[i] = z;   // buffer 0 = h_0 (zeros are swizzle-invariant)
        g_h1[i] = z;
        if (i < NCTA * 8) {
            g_flagA[i] = 0u;
            g_flagB[i] = 0u;
        }
    }
}

// no-op spacer so rnn_scan is the 4th launch (ncu captures launch #4)
__global__ void spacer_kernel() {}

// ---------------- phase 1: xp[t][j][b] = (x @ W_ih^T + b_ih + b_hh)^T ----------------
__global__ void __launch_bounds__(256, 1)
xp_gemm_kernel(const float* __restrict__ b_ih, const float* __restrict__ b_hh) {
    extern __shared__ __align__(16) unsigned char smem_raw[];
    __nv_bfloat16* sx0 = reinterpret_cast<__nv_bfloat16*>(smem_raw);
    __nv_bfloat16* sx1 = sx0 + 64 * 264;
    __nv_bfloat16* sw0 = sx1 + 64 * 264;
    __nv_bfloat16* sw1 = sw0 + 64 * 264;

    const int mt = blockIdx.x;   // = t (64 batch rows)
    const int nt = blockIdx.y;   // hidden tile

    copy_tile<256, 264>(sx0, g_x0 + (size_t)(mt * 64) * II, II);
    copy_tile<256, 264>(sx1, g_x1 + (size_t)(mt * 64) * II, II);
    copy_tile<256, 264>(sw0, g_wih0 + (size_t)(nt * 64) * II, II);
    copy_tile<256, 264>(sw1, g_wih1 + (size_t)(nt * 64) * II, II);
    __syncthreads();

    const int warp = threadIdx.x >> 5, lane = threadIdx.x & 31;
    const int m0 = (warp >> 1) << 4;
    const int n0 = (warp & 1) << 5;
    const int gr = lane >> 2;
    const int qc = (lane & 3) << 1;

    float d[4][4] = {};
#pragma unroll
    for (int seg = 0; seg < 3; ++seg) {
        const __nv_bfloat16* A = (seg < 2) ? sx0 : sx1;
        const __nv_bfloat16* Bm = (seg == 1) ? sw1 : sw0;
        const __nv_bfloat16* ar = A + (m0 + gr) * 264 + qc;
#pragma unroll 4
        for (int kk = 0; kk < 256; kk += 16) {
            unsigned a0 = *reinterpret_cast<const unsigned*>(ar + kk);
            unsigned a1 = *reinterpret_cast<const unsigned*>(ar + kk + 8 * 264);
            unsigned a2 = *reinterpret_cast<const unsigned*>(ar + kk + 8);
            unsigned a3 = *reinterpret_cast<const unsigned*>(ar + kk + 8 * 264 + 8);
#pragma unroll
            for (int nj = 0; nj < 4; ++nj) {
                const __nv_bfloat16* bp = Bm + (n0 + nj * 8 + gr) * 264 + kk + qc;
                unsigned b0 = *reinterpret_cast<const unsigned*>(bp);
                unsigned b1 = *reinterpret_cast<const unsigned*>(bp + 8);
                mma16816(d[nj][0], d[nj][1], d[nj][2], d[nj][3], a0, a1, a2, a3, b0, b1);
            }
        }
    }

    // transposed store: xp[t=mt][j][b]
    const int bb = m0 + gr;
    const int colg = nt * 64 + n0 + qc;
    float* outb = g_xp + (size_t)mt * (BB * HH);
#pragma unroll
    for (int nj = 0; nj < 4; ++nj) {
        int j = colg + nj * 8;
        float bsA = b_ih[j] + b_hh[j];
        float bsB = b_ih[j + 1] + b_hh[j + 1];
        outb[(size_t)j * 64 + bb] = d[nj][0] + bsA;
        outb[(size_t)(j + 1) * 64 + bb] = d[nj][1] + bsB;
        outb[(size_t)j * 64 + bb + 8] = d[nj][2] + bsA;
        outb[(size_t)(j + 1) * 64 + bb + 8] = d[nj][3] + bsB;
    }
}

// ---------------- phase 2: persistent scan, p2p flags + bulk-DMA h exchange ----------------
// smem layout: [0,16K) sh0  [16K,32K) sh1  [32K, +34816) W tiles  [67584] mbarrier
__global__ void __launch_bounds__(256, 1) rnn_scan_kernel() {
    extern __shared__ __align__(16) unsigned char smem_raw[];
    const uint32_t sbase = smem_u32(smem_raw);
    const uint32_t uSH0 = sbase;            // 16KB swizzled h0 k-window
    const uint32_t uSH1 = sbase + 16384;    // 16KB swizzled h1 k-window
    __nv_bfloat16* sw0 = reinterpret_cast<__nv_bfloat16*>(smem_raw + 32768);   // 64 x 136
    __nv_bfloat16* sw1 = sw0 + 64 * 136;
    const uint32_t mbar = sbase + 67584;

    const int tid = threadIdx.x;
    const int bid = blockIdx.x;
    const int nt = bid >> 3;
    const int ks = bid & 7;

    copy_tile<128, 136>(sw0, g_whh0 + (size_t)(nt * 64) * HH + ks * 128, HH);
    copy_tile<128, 136>(sw1, g_whh1 + (size_t)(nt * 64) * HH + ks * 128, HH);
    if (tid == 0)
        asm volatile("mbarrier.init.shared.b64 [%0], %1;" ::"r"(mbar), "r"(1u) : "memory");
    __syncthreads();

    const int warp = tid >> 5, lane = tid & 31;
    const int m0 = (warp >> 1) << 4;   // j sub-tile
    const int n0 = (warp & 1) << 5;    // b half
    const int gr = lane >> 2;
    const int qc = (lane & 3) << 1;

    // hoist W fragments into registers for all 512 steps
    const uint32_t uW0 = smem_u32(sw0), uW1 = smem_u32(sw1);
    const uint32_t a_off = (uint32_t)((m0 + (lane & 15)) * 272 + (lane >> 4) * 16);
    unsigned W0f[8][4], W1f[8][4];
#pragma unroll
    for (int kk = 0; kk < 8; ++kk) {
        ldsm_x4(W0f[kk][0], W0f[kk][1], W0f[kk][2], W0f[kk][3], uW0 + a_off + kk * 32);
        ldsm_x4(W1f[kk][0], W1f[kk][1], W1f[kk][2], W1f[kk][3], uW1 + a_off + kk * 32);
    }

    // swizzled ldsm bases for h tiles (128B rows, SW128 XOR; constant per lane)
    const uint32_t raw1 = (uint32_t)((lane & 15) * 128 + (((lane >> 4) << 3) + n0) * 2);
    const uint32_t raw2 = raw1 + 32;
    const uint32_t hA = raw1 ^ ((raw1 >> 3) & 0x70);
    const uint32_t hB = raw2 ^ ((raw2 >> 3) & 0x70);

    unsigned* const fA_my = g_flagA + bid * 8;
    unsigned* const fB_my = g_flagB + bid * 8;
    const unsigned* const fB_poll = g_flagB + (ks * 16 + (tid & 15)) * 8;
    const unsigned* const fA_poll = g_flagA + (nt * 8 + (tid & 7)) * 8;
    const int slice = bid * 512 + tid * 2;

    for (int t = 0; t < TT; ++t) {
        const unsigned p = (unsigned)(t & 1);

        // ---- wait h_t (16 producer flags; trivially satisfied at t=0) ----
        if (tid < 16) {
            while (ld_acq(fB_poll) != p) {}
        }
        __syncthreads();

        // ---- bulk-DMA h k-window (2 x 16KB, pre-swizzled in gmem) ----
        if (tid == 0) {
            const char* s0 = reinterpret_cast<const char*>(g_h0) + (t % 3) * 131072 + ks * 16384;
            const char* s1 = reinterpret_cast<const char*>(g_h1) + (t % 3) * 131072 + ks * 16384;
            asm volatile("mbarrier.arrive.expect_tx.shared.b64 _, [%0], %1;"
                         ::"r"(mbar), "r"(32768u) : "memory");
            asm volatile(
                "cp.async.bulk.shared::cluster.global.mbarrier::complete_tx::bytes "
                "[%0], [%1], %2, [%3];"
                ::"r"(uSH0), "l"(s0), "r"(16384u), "r"(mbar) : "memory");
            asm volatile(
                "cp.async.bulk.shared::cluster.global.mbarrier::complete_tx::bytes "
                "[%0], [%1], %2, [%3];"
                ::"r"(uSH1), "l"(s1), "r"(16384u), "r"(mbar) : "memory");
        }
        // prefetch xp[t] slice for reduce stage while DMA runs
        float2 acc = *reinterpret_cast<const float2*>(g_xp + (size_t)t * (BB * HH) + slice);
        // wait DMA completion (phase parity = t&1)
        {
            const uint32_t ph = p;
            asm volatile(
                "{\n\t.reg .pred P;\n\tWL%=:\n\t"
                "mbarrier.try_wait.parity.shared.b64 P, [%0], %1;\n\t"
                "@P bra.uni WD%=;\n\tbra.uni WL%=;\n\tWD%=:\n\t}"
                ::"r"(mbar), "r"(ph) : "memory");
        }

        // ---- MMA: D[j16 x b32] += W0*h0 + W1*h0 + W0*h1 ----
        float d[4][4] = {};
#pragma unroll
        for (int kk = 0; kk < 8; ++kk) {
            unsigned r0, r1, r2, r3, s0, s1, s2, s3;
            ldsm_x4t(r0, r1, r2, r3, uSH0 + hA + kk * 2048);
            ldsm_x4t(s0, s1, s2, s3, uSH0 + hB + kk * 2048);
            mma16816(d[0][0], d[0][1], d[0][2], d[0][3],
                     W0f[kk][0], W0f[kk][1], W0f[kk][2], W0f[kk][3], r0, r1);
            mma16816(d[1][0], d[1][1], d[1][2], d[1][3],
                     W0f[kk][0], W0f[kk][1], W0f[kk][2], W0f[kk][3], r2, r3);
            mma16816(d[2][0], d[2][1], d[2][2], d[2][3],
                     W0f[kk][0], W0f[kk][1], W0f[kk][2], W0f[kk][3], s0, s1);
            mma16816(d[3][0], d[3][1], d[3][2], d[3][3],
                     W0f[kk][0], W0f[kk][1], W0f[kk][2], W0f[kk][3], s2, s3);
            mma16816(d[0][0], d[0][1], d[0][2], d[0][3],
                     W1f[kk][0], W1f[kk][1], W1f[kk][2], W1f[kk][3], r0, r1);
            mma16816(d[1][0], d[1][1], d[1][2], d[1][3],
                     W1f[kk][0], W1f[kk][1], W1f[kk][2], W1f[kk][3], r2, r3);
            mma16816(d[2][0], d[2][1], d[2][2], d[2][3],
                     W1f[kk][0], W1f[kk][1], W1f[kk][2], W1f[kk][3], s0, s1);
            mma16816(d[3][0], d[3][1], d[3][2], d[3][3],
                     W1f[kk][0], W1f[kk][1], W1f[kk][2], W1f[kk][3], s2, s3);
        }
#pragma unroll
        for (int kk = 0; kk < 8; ++kk) {
            unsigned r0, r1, r2, r3, s0, s1, s2, s3;
            ldsm_x4t(r0, r1, r2, r3, uSH1 + hA + kk * 2048);
            ldsm_x4t(s0, s1, s2, s3, uSH1 + hB + kk * 2048);
            mma16816(d[0][0], d[0][1], d[0][2], d[0][3],
                     W0f[kk][0], W0f[kk][1], W0f[kk][2], W0f[kk][3], r0, r1);
            mma16816(d[1][0], d[1][1], d[1][2], d[1][3],
                     W0f[kk][0], W0f[kk][1], W0f[kk][2], W0f[kk][3], r2, r3);
            mma16816(d[2][0], d[2][1], d[2][2], d[2][3],
                     W0f[kk][0], W0f[kk][1], W0f[kk][2], W0f[kk][3], s0, s1);
            mma16816(d[3][0], d[3][1], d[3][2], d[3][3],
                     W0f[kk][0], W0f[kk][1], W0f[kk][2], W0f[kk][3], s2, s3);
        }

        // ---- store partials [parity][ks][j][b] ----
        float* Pp = g_part + ((size_t)p * 8 + ks) * (BB * HH) +
                    (size_t)(nt * 64 + m0 + gr) * 64 + n0 + qc;
#pragma unroll
        for (int nj = 0; nj < 4; ++nj) {
            *reinterpret_cast<float2*>(Pp + nj * 8) = make_float2(d[nj][0], d[nj][1]);
            *reinterpret_cast<float2*>(Pp + nj * 8 + 8 * 64) = make_float2(d[nj][2], d[nj][3]);
        }
        __syncthreads();
        if (tid == 0) st_rel(fA_my, p ^ 1u);

        // ---- wait partials of my nt-group (8 flags, includes own) ----
        if (tid < 8) {
            while (ld_acq(fA_poll) != (p ^ 1u)) {}
        }
        __syncthreads();

        // ---- reduce + tanh + split; write h_{t+1} pre-swizzled into buffer (t+1)%3 ----
        {
            float sx = acc.x, sy = acc.y;
#pragma unroll
            for (int s = 0; s < 8; ++s) {
                float2 q = *reinterpret_cast<const float2*>(
                    g_part + ((size_t)p * 8 + s) * (BB * HH) + slice);
                sx += q.x;
                sy += q.y;
            }
            float hx = tanhf(sx), hy = tanhf(sy);
            const int j = slice >> 6, b = slice & 63;
            uint32_t raw = (uint32_t)((j & 127) * 128 + b * 2);
            uint32_t boff = (uint32_t)(((t + 1) % 3) * 131072 + (j >> 7) * 16384) +
                            (raw ^ ((raw >> 3) & 0x70));
            __nv_bfloat162 v0;
            v0.x = __float2bfloat16(hx);
            v0.y = __float2bfloat16(hy);
            *reinterpret_cast<__nv_bfloat162*>(reinterpret_cast<char*>(g_h0) + boff) = v0;
            __nv_bfloat162 v1;
            v1.x = __float2bfloat16(hx - __bfloat162float(v0.x));
            v1.y = __float2bfloat16(hy - __bfloat162float(v0.y));
            *reinterpret_cast<__nv_bfloat162*>(reinterpret_cast<char*>(g_h1) + boff) = v1;
            if (t == TT - 1) {   // h_512 transposed [b][j] in f32
                g_hT[(size_t)b * HH + j] = hx;
                g_hT[(size_t)(b + 1) * HH + j] = hy;
            }
        }
        __syncthreads();
        if (tid == 0) st_rel(fB_my, p ^ 1u);
    }
}

// ---------------- phase 3: out = h_last @ W_lin^T + b_lin ----------------
__global__ void final_linear_kernel(const float* __restrict__ wlin,
                                    const float* __restrict__ blin,
                                    float* __restrict__ out) {
    int gw = (blockIdx.x * 256 + threadIdx.x) >> 5;
    int lane = threadIdx.x & 31;
    int b = gw >> 7;
    int o = gw & (OO - 1);
    const float* wr = wlin + (size_t)o * HH;
    const float* hr = g_hT + (size_t)b * HH;
    float sum = 0.0f;
#pragma unroll 8
    for (int k = lane; k < HH; k += 32) sum += hr[k] * wr[k];
#pragma unroll
    for (int off = 16; off > 0; off >>= 1) sum += __shfl_down_sync(0xffffffffu, sum, off);
    if (lane == 0) out[b * OO + o] = sum + blin[o];
}

// ---------------- launch ----------------
extern "C" void kernel_launch(void* const* d_in, const int* in_sizes, int n_in,
                              void* d_out, int out_size) {
    (void)in_sizes; (void)n_in; (void)out_size;
    const float* x     = (const float*)d_in[0];
    const float* W_ih  = (const float*)d_in[1];
    const float* W_hh  = (const float*)d_in[2];
    const float* b_ih  = (const float*)d_in[3];
    const float* b_hh  = (const float*)d_in[4];
    const float* W_lin = (const float*)d_in[5];
    const float* b_lin = (const float*)d_in[6];
    float* out = (float*)d_out;

    const int scan_smem = 67648;   // 32KB h tiles + 34816B W tiles + mbarrier
    cudaFuncSetAttribute(xp_gemm_kernel, cudaFuncAttributeMaxDynamicSharedMemorySize,
                         4 * 64 * 264 * 2);
    cudaFuncSetAttribute(rnn_scan_kernel, cudaFuncAttributeMaxDynamicSharedMemorySize,
                         scan_smem);

    fused_prep_kernel<<<38144, 256>>>(x, W_ih, W_hh);                     // launch 1
    xp_gemm_kernel<<<dim3(512, 16), 256, 4 * 64 * 264 * 2>>>(b_ih, b_hh); // launch 2
    spacer_kernel<<<1, 32>>>();                                           // launch 3
    rnn_scan_kernel<<<NCTA, 256, scan_smem>>>();                          // launch 4 (ncu target)
    final_linear_kernel<<<(BB * OO * 32) / 256, 256>>>(W_lin, b_lin, out);
}